// round 15
// baseline (speedup 1.0000x reference)
#include <cuda_runtime.h>
#include <cuda_fp16.h>

#define NMAX 100000
#define EMAX 1600000

// ---------------- device scratch (static, no allocation) ----------------
__device__ __align__(16) int    g_deg[NMAX];
__device__ __align__(16) float  g_dis[NMAX];
__device__ __align__(16) int    g_ptr[NMAX];
__device__ __align__(16) int    g_cur[NMAX];
__device__ __align__(16) int    g_src[EMAX];
__device__ int    g_total;
__device__ __align__(16) __half g_hwh[(size_t)NMAX * 128];   // feature buffer A (fp16)
__device__ __align__(16) __half g_hwh2[(size_t)NMAX * 128];  // feature buffer B (fp16)
__device__ __align__(16) __half g_af[(size_t)NMAX * 128];    // activated features fp16
__device__ __align__(16) float  g_h10[(size_t)NMAX * 10];
__device__ __align__(16) float  g_a10[(size_t)NMAX * 10];

// ---------------- helpers ----------------
__device__ __forceinline__ float tf32r(float v) {
    unsigned r; asm("cvt.rna.tf32.f32 %0, %1;" : "=r"(r) : "f"(v));
    return __uint_as_float(r);
}
__device__ __forceinline__ void mma_tf32(float* c, const unsigned* a, const unsigned* b) {
    asm("mma.sync.aligned.m16n8k8.row.col.f32.tf32.tf32.f32 "
        "{%0,%1,%2,%3}, {%4,%5,%6,%7}, {%8,%9}, {%0,%1,%2,%3};"
        : "+f"(c[0]), "+f"(c[1]), "+f"(c[2]), "+f"(c[3])
        : "r"(a[0]), "r"(a[1]), "r"(a[2]), "r"(a[3]), "r"(b[0]), "r"(b[1]));
}

// ---------------- graph preprocessing ----------------
__global__ void k_count(const int* __restrict__ ei, int E) {
    int base = (blockIdx.x * blockDim.x + threadIdx.x) * 4;
    if (base == 0) g_total = 0;
    if (base + 3 < E) {
        int c0 = __ldg(&ei[(size_t)E + base]);
        int c1 = __ldg(&ei[(size_t)E + base + 1]);
        int c2 = __ldg(&ei[(size_t)E + base + 2]);
        int c3 = __ldg(&ei[(size_t)E + base + 3]);
        atomicAdd(&g_deg[c0], 1);
        atomicAdd(&g_deg[c1], 1);
        atomicAdd(&g_deg[c2], 1);
        atomicAdd(&g_deg[c3], 1);
    } else {
        for (int e = base; e < E; ++e) atomicAdd(&g_deg[__ldg(&ei[(size_t)E + e])], 1);
    }
}

__global__ void k_alloc(int N) {
    __shared__ int s[256];
    __shared__ int base;
    int tid = threadIdx.x;
    int i = blockIdx.x * 256 + tid;
    int d = (i < N) ? g_deg[i] : 0;
    if (i < N) g_dis[i] = rsqrtf((float)(d + 1));
    s[tid] = d;
    __syncthreads();
    #pragma unroll
    for (int off = 1; off < 256; off <<= 1) {
        int v = (tid >= off) ? s[tid - off] : 0;
        __syncthreads();
        s[tid] += v;
        __syncthreads();
    }
    if (tid == 255) base = atomicAdd(&g_total, s[255]);
    __syncthreads();
    if (i < N) {
        int p = base + s[tid] - d;
        g_ptr[i] = p;
        g_cur[i] = p;
    }
}

__global__ void k_fill(const int* __restrict__ ei, int E) {
    int base = (blockIdx.x * blockDim.x + threadIdx.x) * 4;
    if (base + 3 < E) {
        int r0 = __ldg(&ei[base]);
        int r1 = __ldg(&ei[base + 1]);
        int r2 = __ldg(&ei[base + 2]);
        int r3 = __ldg(&ei[base + 3]);
        int c0 = __ldg(&ei[(size_t)E + base]);
        int c1 = __ldg(&ei[(size_t)E + base + 1]);
        int c2 = __ldg(&ei[(size_t)E + base + 2]);
        int c3 = __ldg(&ei[(size_t)E + base + 3]);
        int p0 = atomicAdd(&g_cur[c0], 1);
        int p1 = atomicAdd(&g_cur[c1], 1);
        int p2 = atomicAdd(&g_cur[c2], 1);
        int p3 = atomicAdd(&g_cur[c3], 1);
        g_src[p0] = r0;
        g_src[p1] = r1;
        g_src[p2] = r2;
        g_src[p3] = r3;
    } else {
        for (int e = base; e < E; ++e) {
            int r = __ldg(&ei[e]);
            int c = __ldg(&ei[(size_t)E + e]);
            int p = atomicAdd(&g_cur[c], 1);
            g_src[p] = r;
        }
    }
}

// ---------------- spmm row helpers (fp16 gather, fp32 accum) ----------------
__device__ __forceinline__ void add_row(float4& s, const uint2* hp, size_t idx) {
    uint2 w = __ldg(&hp[idx]);
    float2 f0 = __half22float2(*(const __half2*)&w.x);
    float2 f1 = __half22float2(*(const __half2*)&w.y);
    s.x += f0.x; s.y += f0.y; s.z += f1.x; s.w += f1.y;
}
__device__ __forceinline__ void add_row_s(float4& s, const uint2* hp, size_t idx, float d) {
    uint2 w = __ldg(&hp[idx]);
    float2 f0 = __half22float2(*(const __half2*)&w.x);
    float2 f1 = __half22float2(*(const __half2*)&w.y);
    s.x += f0.x * d; s.y += f0.y * d; s.z += f1.x * d; s.w += f1.y * d;
}

// spmm for one node (one warp): result -> g_af[node]
__device__ __forceinline__ void spmm_node(const __half* __restrict__ hsrc,
                                          const float* __restrict__ bias,
                                          int scaled, int node, int lane) {
    const uint2* hp = (const uint2*)hsrc;
    float di = g_dis[node];
    float4 s = make_float4(0.f, 0.f, 0.f, 0.f);
    if (scaled) add_row(s, hp, (size_t)node * 32 + lane);
    else        add_row_s(s, hp, (size_t)node * 32 + lane, di);
    int beg = g_ptr[node];
    int end = beg + g_deg[node];
    int p = beg;
    if (scaled) {
        for (; p + 3 < end; p += 4) {
            int s0 = __ldg(&g_src[p]);
            int s1 = __ldg(&g_src[p + 1]);
            int s2 = __ldg(&g_src[p + 2]);
            int s3 = __ldg(&g_src[p + 3]);
            add_row(s, hp, (size_t)s0 * 32 + lane);
            add_row(s, hp, (size_t)s1 * 32 + lane);
            add_row(s, hp, (size_t)s2 * 32 + lane);
            add_row(s, hp, (size_t)s3 * 32 + lane);
        }
        for (; p < end; ++p) add_row(s, hp, (size_t)__ldg(&g_src[p]) * 32 + lane);
    } else {
        for (; p + 3 < end; p += 4) {
            int s0 = __ldg(&g_src[p]);
            int s1 = __ldg(&g_src[p + 1]);
            int s2 = __ldg(&g_src[p + 2]);
            int s3 = __ldg(&g_src[p + 3]);
            float d0 = __ldg(&g_dis[s0]);
            float d1 = __ldg(&g_dis[s1]);
            float d2 = __ldg(&g_dis[s2]);
            float d3 = __ldg(&g_dis[s3]);
            add_row_s(s, hp, (size_t)s0 * 32 + lane, d0);
            add_row_s(s, hp, (size_t)s1 * 32 + lane, d1);
            add_row_s(s, hp, (size_t)s2 * 32 + lane, d2);
            add_row_s(s, hp, (size_t)s3 * 32 + lane, d3);
        }
        for (; p < end; ++p) {
            int s0 = __ldg(&g_src[p]);
            add_row_s(s, hp, (size_t)s0 * 32 + lane, __ldg(&g_dis[s0]));
        }
    }
    float4 b4 = *(const float4*)&bias[lane * 4];
    float a0 = fmaxf(s.x * di + b4.x, 0.f);
    float a1 = fmaxf(s.y * di + b4.y, 0.f);
    float a2 = fmaxf(s.z * di + b4.z, 0.f);
    float a3 = fmaxf(s.w * di + b4.w, 0.f);
    __half2 h0 = __floats2half2_rn(a0, a1);
    __half2 h1 = __floats2half2_rn(a2, a3);
    uint2 u = make_uint2(*(unsigned*)&h0, *(unsigned*)&h1);
    *(uint2*)&g_af[(size_t)node * 128 + lane * 4] = u;
}

// ---------------- tf32 GEMM core (round-7 mainloop) ----------------
#define WS_STRIDE 132
#define AS_STRIDE 36
#define SMEM_W_ELEMS (128 * WS_STRIDE)
#define SMEM_A_ELEMS (128 * AS_STRIDE)
#define GEMM_SMEM_BYTES ((SMEM_W_ELEMS + SMEM_A_ELEMS) * 4)

// stage W[k][n] tf32 into smem (no sync)
__device__ __forceinline__ void stage_W(float* Ws, const float* __restrict__ W, int tid) {
    #pragma unroll
    for (int i = tid * 4; i < 128 * 128; i += 1024) {
        float4 v = *(const float4*)&W[i];
        v.x = tf32r(v.x); v.y = tf32r(v.y); v.z = tf32r(v.z); v.w = tf32r(v.w);
        int r = i >> 7, c = i & 127;
        *(float4*)&Ws[r * WS_STRIDE + c] = v;
    }
}

// GEMM for 128 rows starting at row0, A from (mode? g_af : Aext), out -> hw_dst (fp16, fold by dis optional)
__device__ __forceinline__ void gemm_core(const float* Ws, float* As,
                                          const float* __restrict__ Aext,
                                          __half* __restrict__ hw_dst,
                                          int mode, int fold, int row0, int N, int tid) {
    int wid  = tid >> 5;
    int lane = tid & 31;
    int lr = lane >> 2;
    int lc = lane & 3;
    int warp_m = (wid & 3) * 32;
    int warp_n = (wid >> 2) * 64;

    float acc[2][8][4];
    #pragma unroll
    for (int i = 0; i < 2; ++i)
        #pragma unroll
        for (int j = 0; j < 8; ++j)
            #pragma unroll
            for (int q = 0; q < 4; ++q) acc[i][j][q] = 0.f;

    for (int kb = 0; kb < 4; ++kb) {
        #pragma unroll
        for (int j = 0; j < 4; ++j) {
            int f = tid + 256 * j;
            int r = f >> 3;
            int k4 = (f & 7) * 4;
            int grow = row0 + r;
            float4 v = make_float4(0.f, 0.f, 0.f, 0.f);
            if (mode) {
                if (grow < N) {
                    uint2 u = *(const uint2*)&g_af[(size_t)grow * 128 + kb * 32 + k4];
                    float2 f0 = __half22float2(*(const __half2*)&u.x);
                    float2 f1 = __half22float2(*(const __half2*)&u.y);
                    v = make_float4(f0.x, f0.y, f1.x, f1.y);
                }
            } else {
                if (grow < N) v = *(const float4*)&Aext[(size_t)grow * 128 + kb * 32 + k4];
            }
            v.x = tf32r(v.x); v.y = tf32r(v.y); v.z = tf32r(v.z); v.w = tf32r(v.w);
            *(float4*)&As[r * AS_STRIDE + k4] = v;
        }
        __syncthreads();

        #pragma unroll
        for (int ks = 0; ks < 4; ++ks) {
            unsigned af[2][4];
            #pragma unroll
            for (int i = 0; i < 2; ++i) {
                const float* ab = &As[(warp_m + i * 16 + lr) * AS_STRIDE + ks * 8 + lc];
                af[i][0] = __float_as_uint(ab[0]);
                af[i][1] = __float_as_uint(ab[8 * AS_STRIDE]);
                af[i][2] = __float_as_uint(ab[4]);
                af[i][3] = __float_as_uint(ab[8 * AS_STRIDE + 4]);
            }
            unsigned bf[8][2];
            #pragma unroll
            for (int j = 0; j < 8; ++j) {
                const float* bb = &Ws[(kb * 32 + ks * 8 + lc) * WS_STRIDE + warp_n + j * 8 + lr];
                bf[j][0] = __float_as_uint(bb[0]);
                bf[j][1] = __float_as_uint(bb[4 * WS_STRIDE]);
            }
            #pragma unroll
            for (int i = 0; i < 2; ++i)
                #pragma unroll
                for (int j = 0; j < 8; ++j)
                    mma_tf32(acc[i][j], af[i], bf[j]);
        }
        __syncthreads();
    }

    #pragma unroll
    for (int i = 0; i < 2; ++i) {
        int r0i = row0 + warp_m + i * 16 + lr;
        int r1i = r0i + 8;
        float d0 = 1.f, d1 = 1.f;
        if (fold) {
            d0 = (r0i < N) ? g_dis[r0i] : 0.f;
            d1 = (r1i < N) ? g_dis[r1i] : 0.f;
        }
        #pragma unroll
        for (int j = 0; j < 8; ++j) {
            int col = warp_n + j * 8 + lc * 2;
            if (r0i < N)
                *(__half2*)&hw_dst[(size_t)r0i * 128 + col] =
                    __floats2half2_rn(acc[i][j][0] * d0, acc[i][j][1] * d0);
            if (r1i < N)
                *(__half2*)&hw_dst[(size_t)r1i * 128 + col] =
                    __floats2half2_rn(acc[i][j][2] * d1, acc[i][j][3] * d1);
        }
    }
}

// ---------------- standalone GEMM (layer 1) ----------------
__global__ void __launch_bounds__(256, 2) gemm128(const float* __restrict__ Aext,
                                                  const float* __restrict__ W,
                                                  int mode, int fold, int N) {
    extern __shared__ float smem[];
    float* Ws = smem;
    float* As = smem + SMEM_W_ELEMS;
    int tid = threadIdx.x;
    stage_W(Ws, W, tid);
    gemm_core(Ws, As, Aext, g_hwh, mode, fold, blockIdx.x * 128, N, tid);
}

// ---------------- FUSED: spmm(prev features) -> g_af rows -> gemm -> hw_dst ----------------
// hsrc: gather source (prev layer features). hw_dst: output buffer (must differ from hsrc).
__global__ void __launch_bounds__(256, 2) fused_sg(const __half* __restrict__ hsrc,
                                                   __half* __restrict__ hw_dst,
                                                   const float* __restrict__ W,
                                                   const float* __restrict__ bias,
                                                   int scaled, int N) {
    extern __shared__ float smem[];
    float* Ws = smem;
    float* As = smem + SMEM_W_ELEMS;
    int tid  = threadIdx.x;
    int wid  = tid >> 5;
    int lane = tid & 31;
    int row0 = blockIdx.x * 128;

    stage_W(Ws, W, tid);          // overlaps with spmm phase below

    // phase 1: spmm + bias + relu for this block's 128 rows -> g_af
    #pragma unroll 1
    for (int t = 0; t < 16; ++t) {
        int node = row0 + wid * 16 + t;
        if (node < N) spmm_node(hsrc, bias, scaled, node, lane);
    }
    __syncthreads();   // g_af rows visible block-wide; Ws staged

    // phase 2: gemm for the same 128 rows (reads g_af, writes hw_dst)
    gemm_core(Ws, As, nullptr, hw_dst, 1, 1, row0, N, tid);
}

// ---------------- standalone SpMM (layer-3 propagate, feeds gemm_out) ----------------
__global__ void spmm128(const __half* __restrict__ hsrc, const float* __restrict__ bias,
                        int scaled, int N) {
    int warp = (blockIdx.x * blockDim.x + threadIdx.x) >> 5;
    if (warp >= N) return;
    spmm_node(hsrc, bias, scaled, warp, threadIdx.x & 31);
}

// ---------------- layer 4 GEMM: g_h10[n] = dis[n] * (g_af[n] @ W_out) ----------------
__global__ void gemm_out(const float* __restrict__ W, int N) {
    __shared__ float Ws[128 * 10];
    int tid = threadIdx.x;
    for (int i = tid; i < 1280; i += 256) Ws[i] = W[i];
    __syncthreads();
    int n = blockIdx.x * 256 + tid;
    if (n >= N) return;
    float s[10];
    #pragma unroll
    for (int c = 0; c < 10; ++c) s[c] = 0.f;
    const uint2* a = (const uint2*)&g_af[(size_t)n * 128];
    #pragma unroll 4
    for (int k = 0; k < 128; k += 4) {
        uint2 u = a[k >> 2];
        float2 f0 = __half22float2(*(const __half2*)&u.x);
        float2 f1 = __half22float2(*(const __half2*)&u.y);
        const float* w0 = &Ws[k * 10];
        #pragma unroll
        for (int c = 0; c < 10; ++c)
            s[c] += f0.x * w0[c] + f0.y * w0[10 + c] + f1.x * w0[20 + c] + f1.y * w0[30 + c];
    }
    float dn = g_dis[n];
    float* o = g_h10 + (size_t)n * 10;
    #pragma unroll
    for (int c = 0; c < 10; ++c) o[c] = s[c] * dn;
}

// ---------------- SpMM width 10 (prefolded fp32) ----------------
__global__ void spmm10(int N) {
    int warp = (blockIdx.x * blockDim.x + threadIdx.x) >> 5;
    if (warp >= N) return;
    int lane = threadIdx.x & 31;
    int grp = lane / 10;
    int c = lane - grp * 10;
    bool active = lane < 30;
    float s = 0.f;
    if (active && grp == 0) s = g_h10[(size_t)warp * 10 + c];
    int beg = g_ptr[warp];
    int m = g_deg[warp];
    for (int p = 0; p < m; p += 3) {
        int e = p + grp;
        if (active && e < m) {
            int src = __ldg(&g_src[beg + e]);
            s += g_h10[(size_t)src * 10 + c];
        }
    }
    float s1 = __shfl_sync(0xffffffffu, s, lane + 10);
    float s2 = __shfl_sync(0xffffffffu, s, lane + 20);
    if (lane < 10) g_a10[(size_t)warp * 10 + lane] = (s + s1 + s2) * g_dis[warp];
}

// ---------------- mean pooling ----------------
__device__ __forceinline__ int lower_bound_i(const int* a, int n, int key) {
    int lo = 0, hi = n;
    while (lo < hi) {
        int mid = (lo + hi) >> 1;
        if (a[mid] < key) lo = mid + 1; else hi = mid;
    }
    return lo;
}

__global__ void pool(const int* __restrict__ batch, const float* __restrict__ b_out,
                     float* __restrict__ out, int N) {
    __shared__ float sred[128];
    int g = blockIdx.x;
    int t = threadIdx.x;
    int lo = lower_bound_i(batch, N, g);
    int hi = lower_bound_i(batch, N, g + 1);
    float s = 0.f;
    if (t < 120) {
        int c = t / 12, sl = t % 12;
        for (int i = lo + sl; i < hi; i += 12) s += g_a10[(size_t)i * 10 + c];
    }
    sred[t] = s;
    __syncthreads();
    if (t < 10) {
        float tot = 0.f;
        #pragma unroll
        for (int j = 0; j < 12; ++j) tot += sred[t * 12 + j];
        float cnt = (float)(hi - lo);
        out[g * 10 + t] = (tot + cnt * b_out[t]) / fmaxf(cnt, 1.f);
    }
}

// ---------------- launcher ----------------
extern "C" void kernel_launch(void* const* d_in, const int* in_sizes, int n_in,
                              void* d_out, int out_size) {
    const float* x      = (const float*)d_in[0];
    const int*   ei     = (const int*)d_in[1];
    const int*   batch  = (const int*)d_in[2];
    const float* W_init = (const float*)d_in[3];
    const float* b_init = (const float*)d_in[4];
    const float* W_h0   = (const float*)d_in[5];
    const float* b_h0   = (const float*)d_in[6];
    const float* W_h1   = (const float*)d_in[7];
    const float* b_h1   = (const float*)d_in[8];
    const float* W_out  = (const float*)d_in[9];
    const float* b_out  = (const float*)d_in[10];
    float* out = (float*)d_out;

    int N = in_sizes[0] / 128;
    int E = in_sizes[1] / 2;

    int nb  = (N + 255) / 256;
    int eb4 = (E + 1023) / 1024;
    int gb  = (N + 127) / 128;
    int sb  = (N + 7) / 8;

    static int* deg_ptr = nullptr;
    static __half *hwA = nullptr, *hwB = nullptr;
    static cudaStream_t s2 = nullptr;
    static cudaEvent_t evFork = nullptr, evJoin = nullptr;
    if (!deg_ptr) {
        cudaGetSymbolAddress((void**)&deg_ptr, g_deg);
        cudaGetSymbolAddress((void**)&hwA, g_hwh);
        cudaGetSymbolAddress((void**)&hwB, g_hwh2);
        cudaFuncSetAttribute(gemm128, cudaFuncAttributeMaxDynamicSharedMemorySize, GEMM_SMEM_BYTES);
        cudaFuncSetAttribute(fused_sg, cudaFuncAttributeMaxDynamicSharedMemorySize, GEMM_SMEM_BYTES);
        cudaStreamCreateWithFlags(&s2, cudaStreamNonBlocking);
        cudaEventCreateWithFlags(&evFork, cudaEventDisableTiming);
        cudaEventCreateWithFlags(&evJoin, cudaEventDisableTiming);
    }

    // fork: preprocessing on side stream, layer-1 GEMM (independent) on main stream
    cudaEventRecord(evFork, 0);
    cudaStreamWaitEvent(s2, evFork, 0);

    cudaMemsetAsync(deg_ptr, 0, (size_t)N * sizeof(int), s2);
    k_count<<<eb4, 256, 0, s2>>>(ei, E);
    k_alloc<<<nb, 256, 0, s2>>>(N);
    k_fill<<<eb4, 256, 0, s2>>>(ei, E);
    cudaEventRecord(evJoin, s2);

    // layer 1 GEMM: raw x @ W_init -> hwA (fold=0, no preproc dependence)
    gemm128<<<gb, 256, GEMM_SMEM_BYTES>>>(x, W_init, 0, 0, N);

    cudaStreamWaitEvent(0, evJoin, 0);

    // fused layer: spmm(hwA, raw -> per-edge dis) + relu(b_init) + gemm(W_h0) -> hwB (dis-folded)
    fused_sg<<<gb, 256, GEMM_SMEM_BYTES>>>(hwA, hwB, W_h0, b_init, 0, N);
    // fused layer: spmm(hwB, prefolded) + relu(b_h0) + gemm(W_h1) -> hwA (dis-folded)
    fused_sg<<<gb, 256, GEMM_SMEM_BYTES>>>(hwB, hwA, W_h1, b_h0, 1, N);
    // layer-3 propagate: spmm(hwA, prefolded) + relu(b_h1) -> g_af
    spmm128<<<sb, 256>>>(hwA, b_h1, 1, N);
    // layer 4 (width 10) + propagate
    gemm_out<<<nb, 256>>>(W_out, N);
    spmm10<<<sb, 256>>>(N);
    // global mean pool (+ b_out)
    pool<<<512, 128>>>(batch, b_out, out, N);
}

// round 16
// speedup vs baseline: 1.2929x; 1.2929x over previous
#include <cuda_runtime.h>
#include <cuda_fp16.h>

#define NMAX 100000
#define EMAX 1600000

// ---------------- device scratch (static, no allocation) ----------------
__device__ __align__(16) int    g_deg[NMAX];
__device__ __align__(16) float  g_dis[NMAX];
__device__ __align__(16) int    g_ptr[NMAX];
__device__ __align__(16) int    g_cur[NMAX];
__device__ __align__(16) int    g_src[EMAX];
__device__ int    g_total;
__device__ __align__(16) __half g_hwh[(size_t)NMAX * 128]; // dis-prefolded features (fp16)
__device__ __align__(16) __half g_af[(size_t)NMAX * 128];  // activated features fp16
__device__ __align__(16) float  g_h10[(size_t)NMAX * 10];  // width-10 prefolded features
__device__ __align__(16) float  g_a10[(size_t)NMAX * 10];  // width-10 propagate result

// ---------------- helpers ----------------
__device__ __forceinline__ float tf32r(float v) {
    unsigned r; asm("cvt.rna.tf32.f32 %0, %1;" : "=r"(r) : "f"(v));
    return __uint_as_float(r);
}
__device__ __forceinline__ void mma_tf32(float* c, const unsigned* a, const unsigned* b) {
    asm("mma.sync.aligned.m16n8k8.row.col.f32.tf32.tf32.f32 "
        "{%0,%1,%2,%3}, {%4,%5,%6,%7}, {%8,%9}, {%0,%1,%2,%3};"
        : "+f"(c[0]), "+f"(c[1]), "+f"(c[2]), "+f"(c[3])
        : "r"(a[0]), "r"(a[1]), "r"(a[2]), "r"(a[3]), "r"(b[0]), "r"(b[1]));
}

// ---------------- graph preprocessing (4 edges/thread) ----------------
__global__ void k_count(const int* __restrict__ ei, int E) {
    int base = (blockIdx.x * blockDim.x + threadIdx.x) * 4;
    if (base == 0) g_total = 0;
    if (base + 3 < E) {
        int c0 = __ldg(&ei[(size_t)E + base]);
        int c1 = __ldg(&ei[(size_t)E + base + 1]);
        int c2 = __ldg(&ei[(size_t)E + base + 2]);
        int c3 = __ldg(&ei[(size_t)E + base + 3]);
        atomicAdd(&g_deg[c0], 1);
        atomicAdd(&g_deg[c1], 1);
        atomicAdd(&g_deg[c2], 1);
        atomicAdd(&g_deg[c3], 1);
    } else {
        for (int e = base; e < E; ++e) atomicAdd(&g_deg[__ldg(&ei[(size_t)E + e])], 1);
    }
}

__global__ void k_alloc(int N) {
    __shared__ int s[256];
    __shared__ int base;
    int tid = threadIdx.x;
    int i = blockIdx.x * 256 + tid;
    int d = (i < N) ? g_deg[i] : 0;
    if (i < N) g_dis[i] = rsqrtf((float)(d + 1));
    s[tid] = d;
    __syncthreads();
    #pragma unroll
    for (int off = 1; off < 256; off <<= 1) {
        int v = (tid >= off) ? s[tid - off] : 0;
        __syncthreads();
        s[tid] += v;
        __syncthreads();
    }
    if (tid == 255) base = atomicAdd(&g_total, s[255]);
    __syncthreads();
    if (i < N) {
        int p = base + s[tid] - d;
        g_ptr[i] = p;
        g_cur[i] = p;
    }
}

__global__ void k_fill(const int* __restrict__ ei, int E) {
    int base = (blockIdx.x * blockDim.x + threadIdx.x) * 4;
    if (base + 3 < E) {
        int r0 = __ldg(&ei[base]);
        int r1 = __ldg(&ei[base + 1]);
        int r2 = __ldg(&ei[base + 2]);
        int r3 = __ldg(&ei[base + 3]);
        int c0 = __ldg(&ei[(size_t)E + base]);
        int c1 = __ldg(&ei[(size_t)E + base + 1]);
        int c2 = __ldg(&ei[(size_t)E + base + 2]);
        int c3 = __ldg(&ei[(size_t)E + base + 3]);
        int p0 = atomicAdd(&g_cur[c0], 1);
        int p1 = atomicAdd(&g_cur[c1], 1);
        int p2 = atomicAdd(&g_cur[c2], 1);
        int p3 = atomicAdd(&g_cur[c3], 1);
        g_src[p0] = r0;
        g_src[p1] = r1;
        g_src[p2] = r2;
        g_src[p3] = r3;
    } else {
        for (int e = base; e < E; ++e) {
            int r = __ldg(&ei[e]);
            int c = __ldg(&ei[(size_t)E + e]);
            int p = atomicAdd(&g_cur[c], 1);
            g_src[p] = r;
        }
    }
}

// ---------------- tf32 GEMM (round-7 config): g_hwh = dis .* (A' @ W), fp16 out ----------------
#define WS_STRIDE 132
#define AS_STRIDE 36
#define SMEM_W_ELEMS (128 * WS_STRIDE)
#define SMEM_A_ELEMS (128 * AS_STRIDE)
#define GEMM_SMEM_BYTES ((SMEM_W_ELEMS + SMEM_A_ELEMS) * 4)

__global__ void __launch_bounds__(256, 2) gemm128(const float* __restrict__ Aext,
                                                  const float* __restrict__ W,
                                                  int mode, int N) {
    extern __shared__ float smem[];
    float* Ws = smem;                    // [k][n] stride 132
    float* As = smem + SMEM_W_ELEMS;     // [m][k] stride 36

    int tid  = threadIdx.x;
    int wid  = tid >> 5;
    int lane = tid & 31;
    int lr = lane >> 2;
    int lc = lane & 3;
    int warp_m = (wid & 3) * 32;
    int warp_n = (wid >> 2) * 64;
    int row0 = blockIdx.x * 128;

    #pragma unroll
    for (int i = tid * 4; i < 128 * 128; i += 1024) {
        float4 v = *(const float4*)&W[i];
        v.x = tf32r(v.x); v.y = tf32r(v.y); v.z = tf32r(v.z); v.w = tf32r(v.w);
        int r = i >> 7, c = i & 127;
        *(float4*)&Ws[r * WS_STRIDE + c] = v;
    }

    float acc[2][8][4];
    #pragma unroll
    for (int i = 0; i < 2; ++i)
        #pragma unroll
        for (int j = 0; j < 8; ++j)
            #pragma unroll
            for (int q = 0; q < 4; ++q) acc[i][j][q] = 0.f;

    for (int kb = 0; kb < 4; ++kb) {
        #pragma unroll
        for (int j = 0; j < 4; ++j) {
            int f = tid + 256 * j;
            int r = f >> 3;
            int k4 = (f & 7) * 4;
            int grow = row0 + r;
            float4 v = make_float4(0.f, 0.f, 0.f, 0.f);
            if (mode) {
                if (grow < N) {
                    uint2 u = *(const uint2*)&g_af[(size_t)grow * 128 + kb * 32 + k4];
                    float2 f0 = __half22float2(*(const __half2*)&u.x);
                    float2 f1 = __half22float2(*(const __half2*)&u.y);
                    v = make_float4(f0.x, f0.y, f1.x, f1.y);
                }
            } else {
                if (grow < N) v = *(const float4*)&Aext[(size_t)grow * 128 + kb * 32 + k4];
            }
            v.x = tf32r(v.x); v.y = tf32r(v.y); v.z = tf32r(v.z); v.w = tf32r(v.w);
            *(float4*)&As[r * AS_STRIDE + k4] = v;
        }
        __syncthreads();

        #pragma unroll
        for (int ks = 0; ks < 4; ++ks) {
            unsigned af[2][4];
            #pragma unroll
            for (int i = 0; i < 2; ++i) {
                const float* ab = &As[(warp_m + i * 16 + lr) * AS_STRIDE + ks * 8 + lc];
                af[i][0] = __float_as_uint(ab[0]);
                af[i][1] = __float_as_uint(ab[8 * AS_STRIDE]);
                af[i][2] = __float_as_uint(ab[4]);
                af[i][3] = __float_as_uint(ab[8 * AS_STRIDE + 4]);
            }
            unsigned bf[8][2];
            #pragma unroll
            for (int j = 0; j < 8; ++j) {
                const float* bb = &Ws[(kb * 32 + ks * 8 + lc) * WS_STRIDE + warp_n + j * 8 + lr];
                bf[j][0] = __float_as_uint(bb[0]);
                bf[j][1] = __float_as_uint(bb[4 * WS_STRIDE]);
            }
            #pragma unroll
            for (int i = 0; i < 2; ++i)
                #pragma unroll
                for (int j = 0; j < 8; ++j)
                    mma_tf32(acc[i][j], af[i], bf[j]);
        }
        __syncthreads();
    }

    // epilogue: fold dis, fp16 store
    #pragma unroll
    for (int i = 0; i < 2; ++i) {
        int r0i = row0 + warp_m + i * 16 + lr;
        int r1i = r0i + 8;
        float d0 = (r0i < N) ? g_dis[r0i] : 0.f;
        float d1 = (r1i < N) ? g_dis[r1i] : 0.f;
        #pragma unroll
        for (int j = 0; j < 8; ++j) {
            int col = warp_n + j * 8 + lc * 2;
            if (r0i < N)
                *(__half2*)&g_hwh[(size_t)r0i * 128 + col] =
                    __floats2half2_rn(acc[i][j][0] * d0, acc[i][j][1] * d0);
            if (r1i < N)
                *(__half2*)&g_hwh[(size_t)r1i * 128 + col] =
                    __floats2half2_rn(acc[i][j][2] * d1, acc[i][j][3] * d1);
        }
    }
}

// ---------------- spmm gather core: returns activated 4 floats for this lane ----------------
__device__ __forceinline__ void add_row(float4& s, const uint2* hp, size_t idx) {
    uint2 w = __ldg(&hp[idx]);
    float2 f0 = __half22float2(*(const __half2*)&w.x);
    float2 f1 = __half22float2(*(const __half2*)&w.y);
    s.x += f0.x; s.y += f0.y; s.z += f1.x; s.w += f1.y;
}

__device__ __forceinline__ float4 gather_act(const float* __restrict__ bias,
                                             int node, int lane, float di) {
    const uint2* hp = (const uint2*)g_hwh;
    float4 s = make_float4(0.f, 0.f, 0.f, 0.f);
    add_row(s, hp, (size_t)node * 32 + lane);     // self-loop (prefolded)
    int beg = g_ptr[node];
    int end = beg + g_deg[node];
    int p = beg;
    for (; p + 3 < end; p += 4) {
        int s0 = __ldg(&g_src[p]);
        int s1 = __ldg(&g_src[p + 1]);
        int s2 = __ldg(&g_src[p + 2]);
        int s3 = __ldg(&g_src[p + 3]);
        add_row(s, hp, (size_t)s0 * 32 + lane);
        add_row(s, hp, (size_t)s1 * 32 + lane);
        add_row(s, hp, (size_t)s2 * 32 + lane);
        add_row(s, hp, (size_t)s3 * 32 + lane);
    }
    for (; p < end; ++p) add_row(s, hp, (size_t)__ldg(&g_src[p]) * 32 + lane);
    float4 b4 = *(const float4*)&bias[lane * 4];
    float4 a;
    a.x = fmaxf(s.x * di + b4.x, 0.f);
    a.y = fmaxf(s.y * di + b4.y, 0.f);
    a.z = fmaxf(s.z * di + b4.z, 0.f);
    a.w = fmaxf(s.w * di + b4.w, 0.f);
    return a;
}

// ---------------- SpMM width 128 (layers 1-2): activated fp16 -> g_af ----------------
__global__ void spmm128(const float* __restrict__ bias, int N) {
    int warp = (blockIdx.x * blockDim.x + threadIdx.x) >> 5;
    if (warp >= N) return;
    int lane = threadIdx.x & 31;
    float di = g_dis[warp];
    float4 a = gather_act(bias, warp, lane, di);
    __half2 h0 = __floats2half2_rn(a.x, a.y);
    __half2 h1 = __floats2half2_rn(a.z, a.w);
    uint2 u = make_uint2(*(unsigned*)&h0, *(unsigned*)&h1);
    *(uint2*)&g_af[(size_t)warp * 128 + lane * 4] = u;
}

// ---------------- FUSED layer-3 propagate + gemm_out: g_h10[n] = dis[n]*(act @ W_out) ----------------
__global__ void spmm_gout(const float* __restrict__ bias, const float* __restrict__ W, int N) {
    __shared__ float Ws[128 * 10];
    int tid = threadIdx.x;
    for (int i = tid; i < 1280; i += 256) Ws[i] = W[i];
    __syncthreads();

    int warp = (blockIdx.x * blockDim.x + tid) >> 5;
    if (warp >= N) return;
    int lane = tid & 31;
    float di = g_dis[warp];
    float4 a = gather_act(bias, warp, lane, di);

    // project 128 -> 10 with warp reduction; act values for k = lane*4 .. lane*4+3
    const float* w0 = &Ws[(lane * 4) * 10];
    float o[10];
    #pragma unroll
    for (int c = 0; c < 10; ++c) {
        float part = a.x * w0[c] + a.y * w0[10 + c] + a.z * w0[20 + c] + a.w * w0[30 + c];
        part += __shfl_xor_sync(0xffffffffu, part, 16);
        part += __shfl_xor_sync(0xffffffffu, part, 8);
        part += __shfl_xor_sync(0xffffffffu, part, 4);
        part += __shfl_xor_sync(0xffffffffu, part, 2);
        part += __shfl_xor_sync(0xffffffffu, part, 1);
        o[c] = part;
    }
    if (lane == 0) {
        float* op = &g_h10[(size_t)warp * 10];
        #pragma unroll
        for (int c = 0; c < 10; ++c) op[c] = o[c] * di;
    }
}

// ---------------- SpMM width 10 (prefolded fp32) ----------------
__global__ void spmm10(int N) {
    int warp = (blockIdx.x * blockDim.x + threadIdx.x) >> 5;
    if (warp >= N) return;
    int lane = threadIdx.x & 31;
    int grp = lane / 10;
    int c = lane - grp * 10;
    bool active = lane < 30;
    float s = 0.f;
    if (active && grp == 0) s = g_h10[(size_t)warp * 10 + c];
    int beg = g_ptr[warp];
    int m = g_deg[warp];
    for (int p = 0; p < m; p += 3) {
        int e = p + grp;
        if (active && e < m) {
            int src = __ldg(&g_src[beg + e]);
            s += g_h10[(size_t)src * 10 + c];
        }
    }
    float s1 = __shfl_sync(0xffffffffu, s, lane + 10);
    float s2 = __shfl_sync(0xffffffffu, s, lane + 20);
    if (lane < 10) g_a10[(size_t)warp * 10 + lane] = (s + s1 + s2) * g_dis[warp];
}

// ---------------- mean pooling ----------------
__device__ __forceinline__ int lower_bound_i(const int* a, int n, int key) {
    int lo = 0, hi = n;
    while (lo < hi) {
        int mid = (lo + hi) >> 1;
        if (a[mid] < key) lo = mid + 1; else hi = mid;
    }
    return lo;
}

__global__ void pool(const int* __restrict__ batch, const float* __restrict__ b_out,
                     float* __restrict__ out, int N) {
    __shared__ float sred[128];
    int g = blockIdx.x;
    int t = threadIdx.x;
    int lo = lower_bound_i(batch, N, g);
    int hi = lower_bound_i(batch, N, g + 1);
    float s = 0.f;
    if (t < 120) {
        int c = t / 12, sl = t % 12;
        for (int i = lo + sl; i < hi; i += 12) s += g_a10[(size_t)i * 10 + c];
    }
    sred[t] = s;
    __syncthreads();
    if (t < 10) {
        float tot = 0.f;
        #pragma unroll
        for (int j = 0; j < 12; ++j) tot += sred[t * 12 + j];
        float cnt = (float)(hi - lo);
        out[g * 10 + t] = (tot + cnt * b_out[t]) / fmaxf(cnt, 1.f);
    }
}

// ---------------- launcher (serial, round-7 structure) ----------------
extern "C" void kernel_launch(void* const* d_in, const int* in_sizes, int n_in,
                              void* d_out, int out_size) {
    const float* x      = (const float*)d_in[0];
    const int*   ei     = (const int*)d_in[1];
    const int*   batch  = (const int*)d_in[2];
    const float* W_init = (const float*)d_in[3];
    const float* b_init = (const float*)d_in[4];
    const float* W_h0   = (const float*)d_in[5];
    const float* b_h0   = (const float*)d_in[6];
    const float* W_h1   = (const float*)d_in[7];
    const float* b_h1   = (const float*)d_in[8];
    const float* W_out  = (const float*)d_in[9];
    const float* b_out  = (const float*)d_in[10];
    float* out = (float*)d_out;

    int N = in_sizes[0] / 128;
    int E = in_sizes[1] / 2;

    int nb  = (N + 255) / 256;
    int eb4 = (E + 1023) / 1024;
    int gb  = (N + 127) / 128;
    int sb  = (N + 7) / 8;

    static int* deg_ptr = nullptr;
    if (!deg_ptr) {
        cudaGetSymbolAddress((void**)&deg_ptr, g_deg);
        cudaFuncSetAttribute(gemm128, cudaFuncAttributeMaxDynamicSharedMemorySize, GEMM_SMEM_BYTES);
    }

    cudaMemsetAsync(deg_ptr, 0, (size_t)N * sizeof(int));
    k_count<<<eb4, 256>>>(ei, E);
    k_alloc<<<nb, 256>>>(N);
    k_fill<<<eb4, 256>>>(ei, E);

    // layer 1: x @ W_init (dis-folded) -> propagate (+b_init, relu)
    gemm128<<<gb, 256, GEMM_SMEM_BYTES>>>(x, W_init, 0, N);
    spmm128<<<sb, 256>>>(b_init, N);
    // layer 2
    gemm128<<<gb, 256, GEMM_SMEM_BYTES>>>(nullptr, W_h0, 1, N);
    spmm128<<<sb, 256>>>(b_h0, N);
    // layer 3 GEMM, then FUSED propagate + width-10 projection
    gemm128<<<gb, 256, GEMM_SMEM_BYTES>>>(nullptr, W_h1, 1, N);
    spmm_gout<<<sb, 256>>>(b_h1, W_out, N);
    // layer-4 propagate (width 10) + pool
    spmm10<<<sb, 256>>>(N);
    pool<<<512, 128>>>(batch, b_out, out, N);
}

// round 17
// speedup vs baseline: 1.3778x; 1.0656x over previous
#include <cuda_runtime.h>
#include <cuda_fp16.h>

#define NMAX 100000
#define EMAX 1600000
#define H10S 16   // padded row stride for width-10 buffers (64B = 2 aligned sectors)

// ---------------- device scratch (static, no allocation) ----------------
__device__ __align__(16) int    g_deg[NMAX];
__device__ __align__(16) float  g_dis[NMAX];
__device__ __align__(16) int    g_ptr[NMAX];
__device__ __align__(16) int    g_cur[NMAX];
__device__ __align__(16) int    g_src[EMAX];
__device__ int    g_total;
__device__ __align__(16) __half g_hwh[(size_t)NMAX * 128]; // dis-prefolded features (fp16)
__device__ __align__(16) __half g_af[(size_t)NMAX * 128];  // activated features fp16
__device__ __align__(16) float  g_h10[(size_t)NMAX * H10S]; // width-10 prefolded (padded rows)
__device__ __align__(16) float  g_a10[(size_t)NMAX * H10S]; // width-10 propagate result (padded)

// ---------------- helpers ----------------
__device__ __forceinline__ float tf32r(float v) {
    unsigned r; asm("cvt.rna.tf32.f32 %0, %1;" : "=r"(r) : "f"(v));
    return __uint_as_float(r);
}
__device__ __forceinline__ void mma_tf32(float* c, const unsigned* a, const unsigned* b) {
    asm("mma.sync.aligned.m16n8k8.row.col.f32.tf32.tf32.f32 "
        "{%0,%1,%2,%3}, {%4,%5,%6,%7}, {%8,%9}, {%0,%1,%2,%3};"
        : "+f"(c[0]), "+f"(c[1]), "+f"(c[2]), "+f"(c[3])
        : "r"(a[0]), "r"(a[1]), "r"(a[2]), "r"(a[3]), "r"(b[0]), "r"(b[1]));
}

// ---------------- graph preprocessing (round-7 exact: 1 edge/thread) ----------------
__global__ void k_count(const int* __restrict__ ei, int E) {
    int e = blockIdx.x * blockDim.x + threadIdx.x;
    if (e == 0) g_total = 0;
    if (e >= E) return;
    atomicAdd(&g_deg[ei[(size_t)E + e]], 1);
}

__global__ void k_alloc(int N) {
    __shared__ int s[256];
    __shared__ int base;
    int tid = threadIdx.x;
    int i = blockIdx.x * 256 + tid;
    int d = (i < N) ? g_deg[i] : 0;
    if (i < N) g_dis[i] = rsqrtf((float)(d + 1));   // +1 self-loop
    s[tid] = d;
    __syncthreads();
    #pragma unroll
    for (int off = 1; off < 256; off <<= 1) {
        int v = (tid >= off) ? s[tid - off] : 0;
        __syncthreads();
        s[tid] += v;
        __syncthreads();
    }
    if (tid == 255) base = atomicAdd(&g_total, s[255]);
    __syncthreads();
    if (i < N) {
        int p = base + s[tid] - d;
        g_ptr[i] = p;
        g_cur[i] = p;
    }
}

__global__ void k_fill(const int* __restrict__ ei, int E) {
    int e = blockIdx.x * blockDim.x + threadIdx.x;
    if (e >= E) return;
    int r = ei[e];
    int c = ei[(size_t)E + e];
    int p = atomicAdd(&g_cur[c], 1);
    g_src[p] = r;
}

// ---------------- tf32 tensor-core GEMM (round-7 exact): g_hwh = dis .* (A' @ W), fp16 out ----------------
// mode 0: A' = Aext (fp32, layer 1).  mode 1: A' = g_af (fp16 activated features).
#define WS_STRIDE 132
#define AS_STRIDE 36
#define SMEM_W_ELEMS (128 * WS_STRIDE)
#define SMEM_A_ELEMS (128 * AS_STRIDE)
#define GEMM_SMEM_BYTES ((SMEM_W_ELEMS + SMEM_A_ELEMS) * 4)

__global__ void __launch_bounds__(256, 2) gemm128(const float* __restrict__ Aext,
                                                  const float* __restrict__ W,
                                                  int mode, int N) {
    extern __shared__ float smem[];
    float* Ws = smem;                    // [k][n] stride 132
    float* As = smem + SMEM_W_ELEMS;     // [m][k] stride 36

    int tid  = threadIdx.x;
    int wid  = tid >> 5;
    int lane = tid & 31;
    int lr = lane >> 2;
    int lc = lane & 3;
    int warp_m = (wid & 3) * 32;
    int warp_n = (wid >> 2) * 64;
    int row0 = blockIdx.x * 128;

    #pragma unroll
    for (int i = tid * 4; i < 128 * 128; i += 1024) {
        float4 v = *(const float4*)&W[i];
        v.x = tf32r(v.x); v.y = tf32r(v.y); v.z = tf32r(v.z); v.w = tf32r(v.w);
        int r = i >> 7, c = i & 127;
        *(float4*)&Ws[r * WS_STRIDE + c] = v;
    }

    float acc[2][8][4];
    #pragma unroll
    for (int i = 0; i < 2; ++i)
        #pragma unroll
        for (int j = 0; j < 8; ++j)
            #pragma unroll
            for (int q = 0; q < 4; ++q) acc[i][j][q] = 0.f;

    for (int kb = 0; kb < 4; ++kb) {
        #pragma unroll
        for (int j = 0; j < 4; ++j) {
            int f = tid + 256 * j;
            int r = f >> 3;
            int k4 = (f & 7) * 4;
            int grow = row0 + r;
            float4 v = make_float4(0.f, 0.f, 0.f, 0.f);
            if (mode) {
                if (grow < N) {
                    uint2 u = *(const uint2*)&g_af[(size_t)grow * 128 + kb * 32 + k4];
                    float2 f0 = __half22float2(*(const __half2*)&u.x);
                    float2 f1 = __half22float2(*(const __half2*)&u.y);
                    v = make_float4(f0.x, f0.y, f1.x, f1.y);
                }
            } else {
                if (grow < N) v = *(const float4*)&Aext[(size_t)grow * 128 + kb * 32 + k4];
            }
            v.x = tf32r(v.x); v.y = tf32r(v.y); v.z = tf32r(v.z); v.w = tf32r(v.w);
            *(float4*)&As[r * AS_STRIDE + k4] = v;
        }
        __syncthreads();

        #pragma unroll
        for (int ks = 0; ks < 4; ++ks) {
            unsigned af[2][4];
            #pragma unroll
            for (int i = 0; i < 2; ++i) {
                const float* ab = &As[(warp_m + i * 16 + lr) * AS_STRIDE + ks * 8 + lc];
                af[i][0] = __float_as_uint(ab[0]);
                af[i][1] = __float_as_uint(ab[8 * AS_STRIDE]);
                af[i][2] = __float_as_uint(ab[4]);
                af[i][3] = __float_as_uint(ab[8 * AS_STRIDE + 4]);
            }
            unsigned bf[8][2];
            #pragma unroll
            for (int j = 0; j < 8; ++j) {
                const float* bb = &Ws[(kb * 32 + ks * 8 + lc) * WS_STRIDE + warp_n + j * 8 + lr];
                bf[j][0] = __float_as_uint(bb[0]);
                bf[j][1] = __float_as_uint(bb[4 * WS_STRIDE]);
            }
            #pragma unroll
            for (int i = 0; i < 2; ++i)
                #pragma unroll
                for (int j = 0; j < 8; ++j)
                    mma_tf32(acc[i][j], af[i], bf[j]);
        }
        __syncthreads();
    }

    #pragma unroll
    for (int i = 0; i < 2; ++i) {
        int r0i = row0 + warp_m + i * 16 + lr;
        int r1i = r0i + 8;
        float d0 = (r0i < N) ? g_dis[r0i] : 0.f;
        float d1 = (r1i < N) ? g_dis[r1i] : 0.f;
        #pragma unroll
        for (int j = 0; j < 8; ++j) {
            int col = warp_n + j * 8 + lc * 2;
            if (r0i < N)
                *(__half2*)&g_hwh[(size_t)r0i * 128 + col] =
                    __floats2half2_rn(acc[i][j][0] * d0, acc[i][j][1] * d0);
            if (r1i < N)
                *(__half2*)&g_hwh[(size_t)r1i * 128 + col] =
                    __floats2half2_rn(acc[i][j][2] * d1, acc[i][j][3] * d1);
        }
    }
}

// ---------------- SpMM width 128 (round-7 exact: fp16 in, fused bias+relu+fp16 out) ----------------
__device__ __forceinline__ void add_row(float4& s, const uint2* hp, size_t idx) {
    uint2 w = __ldg(&hp[idx]);
    float2 f0 = __half22float2(*(const __half2*)&w.x);
    float2 f1 = __half22float2(*(const __half2*)&w.y);
    s.x += f0.x; s.y += f0.y; s.z += f1.x; s.w += f1.y;
}

__global__ void spmm128(const float* __restrict__ bias, int N) {
    int warp = (blockIdx.x * blockDim.x + threadIdx.x) >> 5;
    if (warp >= N) return;
    int lane = threadIdx.x & 31;
    const uint2* hp = (const uint2*)g_hwh;       // 32 uint2 per row
    float4 s = make_float4(0.f, 0.f, 0.f, 0.f);
    add_row(s, hp, (size_t)warp * 32 + lane);    // self-loop term (prefolded)
    int beg = g_ptr[warp];
    int end = beg + g_deg[warp];
    int p = beg;
    for (; p + 3 < end; p += 4) {
        int s0 = __ldg(&g_src[p]);
        int s1 = __ldg(&g_src[p + 1]);
        int s2 = __ldg(&g_src[p + 2]);
        int s3 = __ldg(&g_src[p + 3]);
        add_row(s, hp, (size_t)s0 * 32 + lane);
        add_row(s, hp, (size_t)s1 * 32 + lane);
        add_row(s, hp, (size_t)s2 * 32 + lane);
        add_row(s, hp, (size_t)s3 * 32 + lane);
    }
    for (; p < end; ++p) {
        int s0 = __ldg(&g_src[p]);
        add_row(s, hp, (size_t)s0 * 32 + lane);
    }
    float di = g_dis[warp];
    float4 b4 = *(const float4*)&bias[lane * 4];
    float a0 = fmaxf(s.x * di + b4.x, 0.f);
    float a1 = fmaxf(s.y * di + b4.y, 0.f);
    float a2 = fmaxf(s.z * di + b4.z, 0.f);
    float a3 = fmaxf(s.w * di + b4.w, 0.f);
    __half2 h0 = __floats2half2_rn(a0, a1);
    __half2 h1 = __floats2half2_rn(a2, a3);
    uint2 u = make_uint2(*(unsigned*)&h0, *(unsigned*)&h1);
    *(uint2*)&g_af[(size_t)warp * 128 + lane * 4] = u;
}

// ---------------- layer 4 GEMM: g_h10[n] = dis[n] * (g_af[n] @ W_out), padded rows, uint4 loads ----------------
__global__ void gemm_out(const float* __restrict__ W, int N) {
    __shared__ float Ws[128 * 10];
    int tid = threadIdx.x;
    for (int i = tid; i < 1280; i += 256) Ws[i] = W[i];
    __syncthreads();
    int n = blockIdx.x * 256 + tid;
    if (n >= N) return;
    float s[10];
    #pragma unroll
    for (int c = 0; c < 10; ++c) s[c] = 0.f;
    const uint4* a = (const uint4*)&g_af[(size_t)n * 128];
    #pragma unroll 4
    for (int k = 0; k < 128; k += 8) {
        uint4 u = a[k >> 3];
        float2 f0 = __half22float2(*(const __half2*)&u.x);
        float2 f1 = __half22float2(*(const __half2*)&u.y);
        float2 f2 = __half22float2(*(const __half2*)&u.z);
        float2 f3 = __half22float2(*(const __half2*)&u.w);
        const float* w0 = &Ws[k * 10];
        #pragma unroll
        for (int c = 0; c < 10; ++c)
            s[c] += f0.x * w0[c]      + f0.y * w0[10 + c]
                  + f1.x * w0[20 + c] + f1.y * w0[30 + c]
                  + f2.x * w0[40 + c] + f2.y * w0[50 + c]
                  + f3.x * w0[60 + c] + f3.y * w0[70 + c];
    }
    float dn = g_dis[n];
    float* o = g_h10 + (size_t)n * H10S;
    #pragma unroll
    for (int c = 0; c < 10; ++c) o[c] = s[c] * dn;
}

// ---------------- SpMM width 10 (padded 64B rows -> aligned 2-sector gathers) ----------------
__global__ void spmm10(int N) {
    int warp = (blockIdx.x * blockDim.x + threadIdx.x) >> 5;
    if (warp >= N) return;
    int lane = threadIdx.x & 31;
    int grp = lane / 10;
    int c = lane - grp * 10;
    bool active = lane < 30;
    float s = 0.f;
    if (active && grp == 0) s = g_h10[(size_t)warp * H10S + c];     // self-loop term
    int beg = g_ptr[warp];
    int m = g_deg[warp];
    for (int p = 0; p < m; p += 3) {
        int e = p + grp;
        if (active && e < m) {
            int src = __ldg(&g_src[beg + e]);
            s += __ldg(&g_h10[(size_t)src * H10S + c]);
        }
    }
    float s1 = __shfl_sync(0xffffffffu, s, lane + 10);
    float s2 = __shfl_sync(0xffffffffu, s, lane + 20);
    if (lane < 10) g_a10[(size_t)warp * H10S + lane] = (s + s1 + s2) * g_dis[warp];
}

// ---------------- mean pooling ----------------
__device__ __forceinline__ int lower_bound_i(const int* a, int n, int key) {
    int lo = 0, hi = n;
    while (lo < hi) {
        int mid = (lo + hi) >> 1;
        if (a[mid] < key) lo = mid + 1; else hi = mid;
    }
    return lo;
}

__global__ void pool(const int* __restrict__ batch, const float* __restrict__ b_out,
                     float* __restrict__ out, int N) {
    __shared__ float sred[128];
    int g = blockIdx.x;
    int t = threadIdx.x;
    int lo = lower_bound_i(batch, N, g);
    int hi = lower_bound_i(batch, N, g + 1);
    float s = 0.f;
    if (t < 120) {
        int c = t / 12, sl = t % 12;
        for (int i = lo + sl; i < hi; i += 12) s += g_a10[(size_t)i * H10S + c];
    }
    sred[t] = s;
    __syncthreads();
    if (t < 10) {
        float tot = 0.f;
        #pragma unroll
        for (int j = 0; j < 12; ++j) tot += sred[t * 12 + j];
        float cnt = (float)(hi - lo);
        out[g * 10 + t] = (tot + cnt * b_out[t]) / fmaxf(cnt, 1.f);
    }
}

// ---------------- launcher (round-7 exact serial structure) ----------------
extern "C" void kernel_launch(void* const* d_in, const int* in_sizes, int n_in,
                              void* d_out, int out_size) {
    const float* x      = (const float*)d_in[0];
    const int*   ei     = (const int*)d_in[1];
    const int*   batch  = (const int*)d_in[2];
    const float* W_init = (const float*)d_in[3];
    const float* b_init = (const float*)d_in[4];
    const float* W_h0   = (const float*)d_in[5];
    const float* b_h0   = (const float*)d_in[6];
    const float* W_h1   = (const float*)d_in[7];
    const float* b_h1   = (const float*)d_in[8];
    const float* W_out  = (const float*)d_in[9];
    const float* b_out  = (const float*)d_in[10];
    float* out = (float*)d_out;

    int N = in_sizes[0] / 128;
    int E = in_sizes[1] / 2;

    int nb = (N + 255) / 256;
    int eb = (E + 255) / 256;
    int gb = (N + 127) / 128;
    int sb = (N + 7) / 8;

    static int* deg_ptr = nullptr;
    if (!deg_ptr) {
        cudaGetSymbolAddress((void**)&deg_ptr, g_deg);
        cudaFuncSetAttribute(gemm128, cudaFuncAttributeMaxDynamicSharedMemorySize, GEMM_SMEM_BYTES);
    }

    cudaMemsetAsync(deg_ptr, 0, (size_t)N * sizeof(int));
    k_count<<<eb, 256>>>(ei, E);
    k_alloc<<<nb, 256>>>(N);
    k_fill<<<eb, 256>>>(ei, E);

    // layer 1: x @ W_init (dis-folded) -> propagate (+b_init, relu fused)
    gemm128<<<gb, 256, GEMM_SMEM_BYTES>>>(x, W_init, 0, N);
    spmm128<<<sb, 256>>>(b_init, N);
    // layer 2
    gemm128<<<gb, 256, GEMM_SMEM_BYTES>>>(nullptr, W_h0, 1, N);
    spmm128<<<sb, 256>>>(b_h0, N);
    // layer 3
    gemm128<<<gb, 256, GEMM_SMEM_BYTES>>>(nullptr, W_h1, 1, N);
    spmm128<<<sb, 256>>>(b_h1, N);
    // layer 4 (width 10) + propagate
    gemm_out<<<nb, 256>>>(W_out, N);
    spmm10<<<sb, 256>>>(N);
    // global mean pool (+ b_out)
    pool<<<512, 128>>>(batch, b_out, out, N);
}